// round 12
// baseline (speedup 1.0000x reference)
#include <cuda_runtime.h>

// Problem dims (compile-time constants from the reference)
#define NDIM1 4000
#define NDIM2 4000
#define GDIM  8000
#define RDIM  20000
#define MM1   1200
#define MM2   1200
#define MMG   2400
#define MMR   6000

#define TPB      256
#define COLS_PER_THREAD 4
#define TILE_COLS (TPB * COLS_PER_THREAD)   // 1024

// pair-kernel grid decomposition (col-tiles x row-chunks)
#define T0_CT 8
#define T0_RC 16
#define T1_CT 20
#define T1_RC 16
#define T2_CT 20
#define T2_RC 30
#define T0_B (T0_CT * T0_RC)     // 128
#define T1_B (T1_CT * T1_RC)     // 320
#define T2_B (T2_CT * T2_RC)     // 600
#define MAX_CHUNK 80             // >= ceil(unique rows / RC) for every task

// ---------------- scratch (device globals; no allocation allowed) -----------
// Invariant: all scratch is ZERO on entry to kernel_launch. Module load zeroes
// it initially; each kernel re-zeroes whatever it consumed, so every graph
// replay sees clean state without a dedicated init kernel.
__device__ int    d_cnt1[NDIM1];
__device__ int    d_cnt2[NDIM2];
__device__ int    d_cntg[GDIM];
__device__ int    d_cntr[RDIM];

__device__ float4 d_gmeta[GDIM];   // (p0,p1,p2, w=count) per G column (dense)
__device__ float4 d_rmeta[RDIM];   // (p0,p1,p2, w=count) per R column (dense)

// compacted unique rows (unordered)
__device__ int    d_r1i[MM1];  __device__ float4 d_r1v[MM1];  __device__ float d_r1b[MM1];
__device__ int    d_r2i[MM2];  __device__ float4 d_r2v[MM2];  __device__ float d_r2b[MM2];
__device__ int    d_rgi[MMG];  __device__ float4 d_rgv[MMG];

__device__ int    d_U[4];      // unique counts: rows1, rows2, rowsG
__device__ double d_T[3];      // pair-kernel scalar sums: T1, T2, T3
__device__ double d_sums[64];  // analytic moments

// d_sums layout:
//  col side (G): base 0  : M6(0..5: 00,01,02,11,12,22), Sp(6..8), Sbp(9..11), Sb(12), Sbb(13), norm(14)
//  col side (R): base 16 : same
//  row side 1 :  base 32 : Q2(0..5), Sq(6..8), Sbq(9..11), Sb(12), Sbb(13)
//  row side 2 :  base 48 : same

// ---------------- kernel 1: histograms for all four masks --------------------
__global__ void k_count(const int* __restrict__ m1, const int* __restrict__ m2,
                        const int* __restrict__ mg, const int* __restrict__ mr) {
    int t = blockIdx.x * blockDim.x + threadIdx.x;
    if (t < MM1)                         atomicAdd(&d_cnt1[m1[t]], 1);
    else if (t < MM1 + MM2)              atomicAdd(&d_cnt2[m2[t - MM1]], 1);
    else if (t < MM1 + MM2 + MMG)        atomicAdd(&d_cntg[mg[t - MM1 - MM2]], 1);
    else if (t < MM1 + MM2 + MMG + MMR)  atomicAdd(&d_cntr[mr[t - MM1 - MM2 - MMG]], 1);
}

// ---------------- kernel 2: compact + softmax + moments ----------------------
__device__ __forceinline__ void softmax3(float c0, float c1, float c2,
                                         float& p0, float& p1, float& p2) {
    float m = fmaxf(c0, fmaxf(c1, c2));
    float e0 = expf(c0 - m), e1 = expf(c1 - m), e2 = expf(c2 - m);
    float inv = 1.0f / (e0 + e1 + e2);
    p0 = e0 * inv; p1 = e1 * inv; p2 = e2 * inv;
}

__device__ __forceinline__ float warp_red(float v) {
    v += __shfl_down_sync(0xffffffffu, v, 16);
    v += __shfl_down_sync(0xffffffffu, v, 8);
    v += __shfl_down_sync(0xffffffffu, v, 4);
    v += __shfl_down_sync(0xffffffffu, v, 2);
    v += __shfl_down_sync(0xffffffffu, v, 1);
    return v;
}

// Padded segments (block-aligned so each block has one uniform moment base):
//  [0, 4096)        rows1 (NDIM1=4000 valid)    base 32
//  [4096, 8192)     rows2 (NDIM2=4000 valid)    base 48
//  [8192, 16384)    colsG (GDIM=8000 valid)     base 0
//  [16384, 36608)   colsR (RDIM=20000 valid)    base 16
#define SEG1_END  4096
#define SEG2_END  8192
#define SEGG_END  16384
#define SEGR_END  36608
#define COMPACT_BLOCKS (SEGR_END / TPB)   // 143

__global__ void k_compact(const float* __restrict__ C1, const float* __restrict__ C2,
                          const float* __restrict__ Cg, const float* __restrict__ Cr,
                          const float* __restrict__ Ai,
                          const float* __restrict__ bg, const float* __restrict__ br,
                          const float* __restrict__ b1, const float* __restrict__ b2) {
    __shared__ float s_mom[8][15];
    int t   = blockIdx.x * blockDim.x + threadIdx.x;
    int tid = threadIdx.x;
    int wid = tid >> 5, lane = tid & 31;

    float ch[15];
#pragma unroll
    for (int i = 0; i < 15; i++) ch[i] = 0.f;
    int base;

    if (t < SEG2_END) {
        // row segments
        bool is1 = (t < SEG1_END);
        int v = is1 ? t : (t - SEG1_END);
        base = is1 ? 32 : 48;
        int n = is1 ? NDIM1 : NDIM2;
        if (v < n) {
            int c;
            if (is1) { c = d_cnt1[v]; d_cnt1[v] = 0; }
            else     { c = d_cnt2[v]; d_cnt2[v] = 0; }
            if (c > 0) {
                const float* C  = is1 ? C1 : C2;
                const float* bb = is1 ? b1 : b2;
                float p0, p1, p2;
                softmax3(C[3*v], C[3*v+1], C[3*v+2], p0, p1, p2);
                float q0 = p0*Ai[0] + p1*Ai[3] + p2*Ai[6];
                float q1 = p0*Ai[1] + p1*Ai[4] + p2*Ai[7];
                float q2 = p0*Ai[2] + p1*Ai[5] + p2*Ai[8];
                float bv = bb[v];
                float w  = (float)c;
                int pos = atomicAdd(&d_U[is1 ? 0 : 1], 1);
                float4 rv = make_float4(w*q0, w*q1, w*q2, w);
                if (is1) { d_r1i[pos] = v; d_r1v[pos] = rv; d_r1b[pos] = w*bv; }
                else     { d_r2i[pos] = v; d_r2v[pos] = rv; d_r2b[pos] = w*bv; }
                ch[0] = w*q0*q0; ch[1] = w*q0*q1; ch[2] = w*q0*q2;
                ch[3] = w*q1*q1; ch[4] = w*q1*q2; ch[5] = w*q2*q2;
                ch[6] = w*q0; ch[7] = w*q1; ch[8] = w*q2;
                ch[9] = w*bv*q0; ch[10] = w*bv*q1; ch[11] = w*bv*q2;
                ch[12] = w*bv; ch[13] = w*bv*bv;
            }
        }
    } else {
        // column segments
        bool isG = (t < SEGG_END);
        int v = isG ? (t - SEG2_END) : (t - SEGG_END);
        base = isG ? 0 : 16;
        int n = isG ? GDIM : RDIM;
        if (v < n) {
            const float* C  = isG ? Cg : Cr;
            const float* bb = isG ? bg : br;
            int c;
            if (isG) { c = d_cntg[v]; d_cntg[v] = 0; }
            else     { c = d_cntr[v]; d_cntr[v] = 0; }
            float p0, p1, p2;
            softmax3(C[3*v], C[3*v+1], C[3*v+2], p0, p1, p2);
            float w  = (float)c;
            float bv = bb[v];
            float4 mv = make_float4(p0, p1, p2, w);
            if (isG) {
                d_gmeta[v] = mv;
                if (c > 0) {
                    int pos = atomicAdd(&d_U[2], 1);
                    d_rgi[pos] = v;
                    d_rgv[pos] = make_float4(w*p0, w*p1, w*p2, 0.f);
                }
            } else {
                d_rmeta[v] = mv;
            }
            if (c > 0) {
                ch[0] = w*p0*p0; ch[1] = w*p0*p1; ch[2] = w*p0*p2;
                ch[3] = w*p1*p1; ch[4] = w*p1*p2; ch[5] = w*p2*p2;
                ch[6] = w*p0; ch[7] = w*p1; ch[8] = w*p2;
                ch[9] = w*bv*p0; ch[10] = w*bv*p1; ch[11] = w*bv*p2;
                ch[12] = w*bv; ch[13] = w*bv*bv;
                ch[14] = w*(p0*p0 + p1*p1 + p2*p2);
            }
        }
    }

    // fast block reduce: warp shuffle -> smem -> 15 atomics/block
#pragma unroll
    for (int i = 0; i < 15; i++) {
        float r = warp_red(ch[i]);
        if (lane == 0) s_mom[wid][i] = r;
    }
    __syncthreads();
    if (tid < 15) {
        float tot = 0.f;
#pragma unroll
        for (int w = 0; w < 8; w++) tot += s_mom[w][tid];
        if (tot != 0.f) atomicAdd(&d_sums[base + tid], (double)tot);
    }
}

// ---------------- kernel 3: fused dense pair-sum kernel ----------------------
// task 0: G  rows = unique mask_1 (weighted), cols dense GDIM  -> T1 partial
// task 1: R  rows = unique mask_2 (weighted), cols dense RDIM  -> T2 partial
// task 2: A  rows = unique mask_g (weighted), cols dense RDIM  -> T3 partial
__device__ __forceinline__ float4 ldcs4(const float* p) {
    return __ldcs((const float4*)p);
}

__global__ void __launch_bounds__(TPB, 5)
k_pair(const float* __restrict__ Gm, const float* __restrict__ Rm,
       const float* __restrict__ Am,
       const float* __restrict__ bg, const float* __restrict__ br) {
    __shared__ int    s_off[MAX_CHUNK];   // row element-offsets (idx*ld)
    __shared__ float4 s_rv[MAX_CHUNK];
    __shared__ float  s_wb[MAX_CHUNK];
    __shared__ float  s_red[TPB];

    int bid = blockIdx.x, tid = threadIdx.x;
    int task, ct, rc, RC;
    const float* mat; int ld; const float* cbias; const float4* cmeta;

    if (bid < T0_B) {
        task = 0; ct = bid % T0_CT; rc = bid / T0_CT; RC = T0_RC;
        mat = Gm; ld = GDIM; cbias = bg; cmeta = d_gmeta;
    } else if (bid < T0_B + T1_B) {
        int b = bid - T0_B;
        task = 1; ct = b % T1_CT; rc = b / T1_CT; RC = T1_RC;
        mat = Rm; ld = RDIM; cbias = br; cmeta = d_rmeta;
    } else {
        int b = bid - T0_B - T1_B;
        task = 2; ct = b % T2_CT; rc = b / T2_CT; RC = T2_RC;
        mat = Am; ld = RDIM; cbias = nullptr; cmeta = d_rmeta;
    }

    int u     = d_U[task];                 // unique row count (runtime)
    int chunk = (u + RC - 1) / RC;
    int r0    = rc * chunk;
    int nr    = min(chunk, u - r0);
    if (nr < 0) nr = 0;

    int c0 = ct * TILE_COLS + tid * COLS_PER_THREAD;
    bool colvalid = (c0 + COLS_PER_THREAD <= ld);   // dims are multiples of 4

    // stage row metadata into smem (precompute element offsets)
    for (int j = tid; j < nr; j += TPB) {
        int rr = r0 + j;
        if (task == 0)      { s_off[j] = d_r1i[rr] * GDIM; s_rv[j] = d_r1v[rr]; s_wb[j] = d_r1b[rr]; }
        else if (task == 1) { s_off[j] = d_r2i[rr] * RDIM; s_rv[j] = d_r2v[rr]; s_wb[j] = d_r2b[rr]; }
        else                { s_off[j] = d_rgi[rr] * RDIM; s_rv[j] = d_rgv[rr]; }
    }
    __syncthreads();

    float contrib = 0.f;

    if (colvalid) {
        if (task == 2) {
            float y0[4] = {0,0,0,0}, y1[4] = {0,0,0,0}, y2[4] = {0,0,0,0};
#pragma unroll 4
            for (int j = 0; j < nr; ++j) {
                const float4 x4 = ldcs4(mat + (size_t)(unsigned)s_off[j] + c0);
                float4 rv = s_rv[j];          // (w*p0, w*p1, w*p2, -)
                float xx[4] = {x4.x, x4.y, x4.z, x4.w};
#pragma unroll
                for (int c = 0; c < 4; c++) {
                    y0[c] += rv.x * xx[c];
                    y1[c] += rv.y * xx[c];
                    y2[c] += rv.z * xx[c];
                }
            }
#pragma unroll
            for (int c = 0; c < 4; c++) {
                float4 cm = __ldg(&cmeta[c0 + c]);   // (p0,p1,p2,w)
                contrib += cm.w * (cm.x * y0[c] + cm.y * y1[c] + cm.z * y2[c]);
            }
        } else {
            float y0[4] = {0,0,0,0}, y1[4] = {0,0,0,0}, y2[4] = {0,0,0,0};
            float s1[4] = {0,0,0,0}, sq[4] = {0,0,0,0}, sb[4] = {0,0,0,0};
#pragma unroll 4
            for (int j = 0; j < nr; ++j) {
                const float4 x4 = ldcs4(mat + (size_t)(unsigned)s_off[j] + c0);
                float4 rv = s_rv[j];          // (w*q0, w*q1, w*q2, w)
                float wb  = s_wb[j];          // w*b
                float xx[4] = {x4.x, x4.y, x4.z, x4.w};
#pragma unroll
                for (int c = 0; c < 4; c++) {
                    float x = xx[c];
                    y0[c] += rv.x * x;
                    y1[c] += rv.y * x;
                    y2[c] += rv.z * x;
                    float tw = rv.w * x;
                    s1[c] += tw;
                    sq[c] += tw * x;
                    sb[c] += wb * x;
                }
            }
#pragma unroll
            for (int c = 0; c < 4; c++) {
                float4 cm = __ldg(&cmeta[c0 + c]);
                float bgv = __ldg(&cbias[c0 + c]);
                float dotv = cm.x * y0[c] + cm.y * y1[c] + cm.z * y2[c];
                contrib += cm.w * (sq[c] - 2.f * (dotv + bgv * s1[c] + sb[c]));
            }
        }
    }

    // block reduce -> one double atomic per block
    s_red[tid] = contrib;
    __syncthreads();
    for (int s = TPB / 2; s > 0; s >>= 1) {
        if (tid < s) s_red[tid] += s_red[tid + s];
        __syncthreads();
    }
    if (tid == 0) atomicAdd(&d_T[task], (double)s_red[0]);
}

// ---------------- kernel 4: parallel finalize (+ reset scalar scratch) -------
__device__ __forceinline__ double contract6s(const double* A, const double* B) {
    // symmetric 3x3 stored as (00,01,02,11,12,22)
    return A[0]*B[0] + A[3]*B[3] + A[5]*B[5]
         + 2.0 * (A[1]*B[1] + A[2]*B[2] + A[4]*B[4]);
}
__device__ __forceinline__ double dot3s(const double* a, const double* b) {
    return a[0]*b[0] + a[1]*b[1] + a[2]*b[2];
}

// 96 threads: threads 0-63 stage d_sums, 64-66 stage d_T (latencies overlap);
// thread 0 computes from smem; all threads reset scratch in parallel.
__global__ void k_finalize(float* __restrict__ out) {
    __shared__ double s[64];
    __shared__ double sT[3];
    int tid = threadIdx.x;

    if (tid < 64)                 s[tid] = d_sums[tid];
    else if (tid < 67)            sT[tid - 64] = d_T[tid - 64];
    __syncthreads();

    if (tid == 0) {
        const double* g  = &s[0];
        const double* rr = &s[16];
        const double* r1 = &s[32];
        const double* r2 = &s[48];

        double s1 = sT[0]
                  + contract6s(&r1[0], &g[0])
                  + 2.0 * (dot3s(&r1[6], &g[9]) + dot3s(&r1[9], &g[6]))
                  + ((double)MM1 * g[13] + 2.0 * r1[12] * g[12] + (double)MMG * r1[13]);
        double loss1 = s1 / ((double)MM1 * (double)MMG);

        double s2 = sT[1]
                  + contract6s(&r2[0], &rr[0])
                  + 2.0 * (dot3s(&r2[6], &rr[9]) + dot3s(&r2[9], &rr[6]))
                  + ((double)MM2 * rr[13] + 2.0 * r2[12] * rr[12] + (double)MMR * r2[13]);
        double loss2 = s2 / ((double)MM2 * (double)MMR);

        double loss3 = -sT[2] / sqrt(g[14] * rr[14]);

        double t1 = 1000.0 * loss1;
        double t2 = 1000.0 * loss2;
        double t3 = 100.0  * loss3;
        out[0] = (float)(t1 + t2 + t3);   // ALPHA[3] = 0 -> loss4 contributes nothing
        out[1] = (float)t1;
        out[2] = (float)t2;
        out[3] = (float)t3;
        out[4] = 0.0f;
    }

    // reset scalar scratch for the next graph replay (parallel)
    if (tid < 64)      d_sums[tid] = 0.0;
    else if (tid < 67) d_T[tid - 64] = 0.0;
    else if (tid < 71) d_U[tid - 67] = 0;
}

// ---------------- launch ------------------------------------------------------
extern "C" void kernel_launch(void* const* d_in, const int* in_sizes, int n_in,
                              void* d_out, int out_size) {
    const float* G  = (const float*)d_in[0];
    const float* R  = (const float*)d_in[1];
    const float* A  = (const float*)d_in[2];
    const float* C1 = (const float*)d_in[3];
    const float* C2 = (const float*)d_in[4];
    const float* Cg = (const float*)d_in[5];
    const float* Cr = (const float*)d_in[6];
    const float* Ai = (const float*)d_in[7];
    const float* bg = (const float*)d_in[8];
    const float* br = (const float*)d_in[9];
    const float* b1 = (const float*)d_in[10];
    const float* b2 = (const float*)d_in[11];
    const int*   m1 = (const int*)d_in[12];
    const int*   m2 = (const int*)d_in[13];
    const int*   mg = (const int*)d_in[14];
    const int*   mr = (const int*)d_in[15];
    float* out = (float*)d_out;

    (void)in_sizes; (void)n_in; (void)out_size;

    const int nmask = MM1 + MM2 + MMG + MMR;   // 10800

    k_count<<<(nmask + 255) / 256, 256>>>(m1, m2, mg, mr);
    k_compact<<<COMPACT_BLOCKS, TPB>>>(C1, C2, Cg, Cr, Ai, bg, br, b1, b2);
    k_pair<<<T0_B + T1_B + T2_B, TPB>>>(G, R, A, bg, br);
    k_finalize<<<1, 96>>>(out);
}

// round 14
// speedup vs baseline: 1.0656x; 1.0656x over previous
#include <cuda_runtime.h>

// Problem dims (compile-time constants from the reference)
#define NDIM1 4000
#define NDIM2 4000
#define GDIM  8000
#define RDIM  20000
#define MM1   1200
#define MM2   1200
#define MMG   2400
#define MMR   6000

#define TPB      256
#define COLS_PER_THREAD 4
#define TILE_COLS (TPB * COLS_PER_THREAD)   // 1024

// pair-kernel grid decomposition (col-tiles x row-chunks)
#define T0_CT 8
#define T0_RC 16
#define T1_CT 20
#define T1_RC 16
#define T2_CT 20
#define T2_RC 30
#define T0_B (T0_CT * T0_RC)     // 128
#define T1_B (T1_CT * T1_RC)     // 320
#define T2_B (T2_CT * T2_RC)     // 600
#define TOTAL_B (T0_B + T1_B + T2_B)   // 1048
#define MAX_CHUNK 80             // >= ceil(unique rows / RC) for every task

// ---------------- scratch (device globals; no allocation allowed) -----------
// Invariant: all scratch is ZERO on entry to kernel_launch. Module load zeroes
// it initially; kernels re-zero whatever they consumed, so every graph replay
// sees clean state.
__device__ int    d_cnt1[NDIM1];
__device__ int    d_cnt2[NDIM2];
__device__ int    d_cntg[GDIM];
__device__ int    d_cntr[RDIM];

__device__ float4 d_gmeta[GDIM];   // (p0,p1,p2, w=count) per G column (dense)
__device__ float4 d_rmeta[RDIM];   // (p0,p1,p2, w=count) per R column (dense)

// compacted unique rows (unordered)
__device__ int    d_r1i[MM1];  __device__ float4 d_r1v[MM1];  __device__ float d_r1b[MM1];
__device__ int    d_r2i[MM2];  __device__ float4 d_r2v[MM2];  __device__ float d_r2b[MM2];
__device__ int    d_rgi[MMG];  __device__ float4 d_rgv[MMG];

__device__ int    d_U[4];      // unique counts: rows1, rows2, rowsG
__device__ double d_T[3];      // pair sums: T1, T2, T3raw
__device__ double d_sums[64];  // analytic moments
__device__ int    d_done;      // pair-kernel last-block ticket

// d_sums layout:
//  col side (G): base 0  : M6(0..5: 00,01,02,11,12,22), Sp(6..8), Sbp(9..11), Sb(12), Sbb(13), norm(14)
//  col side (R): base 16 : same
//  row side 1 :  base 32 : Q2(0..5), Sq(6..8), Sbq(9..11), Sb(12), Sbb(13)
//  row side 2 :  base 48 : same

// ---------------- kernel 1: histograms for all four masks --------------------
__global__ void k_count(const int* __restrict__ m1, const int* __restrict__ m2,
                        const int* __restrict__ mg, const int* __restrict__ mr) {
    int t = blockIdx.x * blockDim.x + threadIdx.x;
    if (t < MM1)                         atomicAdd(&d_cnt1[m1[t]], 1);
    else if (t < MM1 + MM2)              atomicAdd(&d_cnt2[m2[t - MM1]], 1);
    else if (t < MM1 + MM2 + MMG)        atomicAdd(&d_cntg[mg[t - MM1 - MM2]], 1);
    else if (t < MM1 + MM2 + MMG + MMR)  atomicAdd(&d_cntr[mr[t - MM1 - MM2 - MMG]], 1);
}

// ---------------- kernel 2: compact + softmax + moments ----------------------
__device__ __forceinline__ void softmax3(float c0, float c1, float c2,
                                         float& p0, float& p1, float& p2) {
    float m = fmaxf(c0, fmaxf(c1, c2));
    float e0 = expf(c0 - m), e1 = expf(c1 - m), e2 = expf(c2 - m);
    float inv = 1.0f / (e0 + e1 + e2);
    p0 = e0 * inv; p1 = e1 * inv; p2 = e2 * inv;
}

__device__ __forceinline__ float warp_red(float v) {
    v += __shfl_down_sync(0xffffffffu, v, 16);
    v += __shfl_down_sync(0xffffffffu, v, 8);
    v += __shfl_down_sync(0xffffffffu, v, 4);
    v += __shfl_down_sync(0xffffffffu, v, 2);
    v += __shfl_down_sync(0xffffffffu, v, 1);
    return v;
}

// Padded segments (block-aligned so each block has one uniform moment base):
//  [0, 4096)        rows1 (NDIM1=4000 valid)    base 32
//  [4096, 8192)     rows2 (NDIM2=4000 valid)    base 48
//  [8192, 16384)    colsG (GDIM=8000 valid)     base 0
//  [16384, 36608)   colsR (RDIM=20000 valid)    base 16
#define SEG1_END  4096
#define SEG2_END  8192
#define SEGG_END  16384
#define SEGR_END  36608
#define COMPACT_BLOCKS (SEGR_END / TPB)   // 143

__global__ void k_compact(const float* __restrict__ C1, const float* __restrict__ C2,
                          const float* __restrict__ Cg, const float* __restrict__ Cr,
                          const float* __restrict__ Ai,
                          const float* __restrict__ bg, const float* __restrict__ br,
                          const float* __restrict__ b1, const float* __restrict__ b2) {
    __shared__ float s_mom[8][15];
    int t   = blockIdx.x * blockDim.x + threadIdx.x;
    int tid = threadIdx.x;
    int wid = tid >> 5, lane = tid & 31;

    float ch[15];
#pragma unroll
    for (int i = 0; i < 15; i++) ch[i] = 0.f;
    int base;

    if (t < SEG2_END) {
        // row segments
        bool is1 = (t < SEG1_END);
        int v = is1 ? t : (t - SEG1_END);
        base = is1 ? 32 : 48;
        int n = is1 ? NDIM1 : NDIM2;
        if (v < n) {
            int c;
            if (is1) { c = d_cnt1[v]; d_cnt1[v] = 0; }
            else     { c = d_cnt2[v]; d_cnt2[v] = 0; }
            if (c > 0) {
                const float* C  = is1 ? C1 : C2;
                const float* bb = is1 ? b1 : b2;
                float p0, p1, p2;
                softmax3(C[3*v], C[3*v+1], C[3*v+2], p0, p1, p2);
                float q0 = p0*Ai[0] + p1*Ai[3] + p2*Ai[6];
                float q1 = p0*Ai[1] + p1*Ai[4] + p2*Ai[7];
                float q2 = p0*Ai[2] + p1*Ai[5] + p2*Ai[8];
                float bv = bb[v];
                float w  = (float)c;
                int pos = atomicAdd(&d_U[is1 ? 0 : 1], 1);
                float4 rv = make_float4(w*q0, w*q1, w*q2, w);
                if (is1) { d_r1i[pos] = v; d_r1v[pos] = rv; d_r1b[pos] = w*bv; }
                else     { d_r2i[pos] = v; d_r2v[pos] = rv; d_r2b[pos] = w*bv; }
                ch[0] = w*q0*q0; ch[1] = w*q0*q1; ch[2] = w*q0*q2;
                ch[3] = w*q1*q1; ch[4] = w*q1*q2; ch[5] = w*q2*q2;
                ch[6] = w*q0; ch[7] = w*q1; ch[8] = w*q2;
                ch[9] = w*bv*q0; ch[10] = w*bv*q1; ch[11] = w*bv*q2;
                ch[12] = w*bv; ch[13] = w*bv*bv;
            }
        }
    } else {
        // column segments
        bool isG = (t < SEGG_END);
        int v = isG ? (t - SEG2_END) : (t - SEGG_END);
        base = isG ? 0 : 16;
        int n = isG ? GDIM : RDIM;
        if (v < n) {
            const float* C  = isG ? Cg : Cr;
            const float* bb = isG ? bg : br;
            int c;
            if (isG) { c = d_cntg[v]; d_cntg[v] = 0; }
            else     { c = d_cntr[v]; d_cntr[v] = 0; }
            float p0, p1, p2;
            softmax3(C[3*v], C[3*v+1], C[3*v+2], p0, p1, p2);
            float w  = (float)c;
            float bv = bb[v];
            float4 mv = make_float4(p0, p1, p2, w);
            if (isG) {
                d_gmeta[v] = mv;
                if (c > 0) {
                    int pos = atomicAdd(&d_U[2], 1);
                    d_rgi[pos] = v;
                    d_rgv[pos] = make_float4(w*p0, w*p1, w*p2, 0.f);
                }
            } else {
                d_rmeta[v] = mv;
            }
            if (c > 0) {
                ch[0] = w*p0*p0; ch[1] = w*p0*p1; ch[2] = w*p0*p2;
                ch[3] = w*p1*p1; ch[4] = w*p1*p2; ch[5] = w*p2*p2;
                ch[6] = w*p0; ch[7] = w*p1; ch[8] = w*p2;
                ch[9] = w*bv*p0; ch[10] = w*bv*p1; ch[11] = w*bv*p2;
                ch[12] = w*bv; ch[13] = w*bv*bv;
                ch[14] = w*(p0*p0 + p1*p1 + p2*p2);
            }
        }
    }

    // fast block reduce: warp shuffle -> smem -> 15 atomics/block
#pragma unroll
    for (int i = 0; i < 15; i++) {
        float r = warp_red(ch[i]);
        if (lane == 0) s_mom[wid][i] = r;
    }
    __syncthreads();
    if (tid < 15) {
        float tot = 0.f;
#pragma unroll
        for (int w = 0; w < 8; w++) tot += s_mom[w][tid];
        if (tot != 0.f) atomicAdd(&d_sums[base + tid], (double)tot);
    }
}

// ---------------- kernel 3: fused pair-sum + last-block finalize -------------
// task 0: G  rows = unique mask_1 (weighted), cols dense GDIM  -> T1 partial
// task 1: R  rows = unique mask_2 (weighted), cols dense RDIM  -> T2 partial
// task 2: A  rows = unique mask_g (weighted), cols dense RDIM  -> T3 partial
// The last block to finish (atomic ticket; no spin-waiting, so safe under any
// block scheduling) computes the final output from d_sums/d_T and resets the
// scalar scratch.
__device__ __forceinline__ float4 ldcs4(const float* p) {
    return __ldcs((const float4*)p);
}

__device__ __forceinline__ double contract6s(const double* A, const double* B) {
    // symmetric 3x3 stored as (00,01,02,11,12,22)
    return A[0]*B[0] + A[3]*B[3] + A[5]*B[5]
         + 2.0 * (A[1]*B[1] + A[2]*B[2] + A[4]*B[4]);
}
__device__ __forceinline__ double dot3s(const double* a, const double* b) {
    return a[0]*b[0] + a[1]*b[1] + a[2]*b[2];
}

__global__ void __launch_bounds__(TPB)
k_pair(const float* __restrict__ Gm, const float* __restrict__ Rm,
       const float* __restrict__ Am,
       const float* __restrict__ bg, const float* __restrict__ br,
       float* __restrict__ out) {
    __shared__ int    s_off[MAX_CHUNK];   // row element-offsets (idx*ld)
    __shared__ float4 s_rv[MAX_CHUNK];
    __shared__ float  s_wb[MAX_CHUNK];
    __shared__ float  s_red[TPB];
    __shared__ int    s_last;
    __shared__ double s_fin[67];

    int bid = blockIdx.x, tid = threadIdx.x;
    int task, ct, rc, RC;
    const float* mat; int ld; const float* cbias; const float4* cmeta;

    if (bid < T0_B) {
        task = 0; ct = bid % T0_CT; rc = bid / T0_CT; RC = T0_RC;
        mat = Gm; ld = GDIM; cbias = bg; cmeta = d_gmeta;
    } else if (bid < T0_B + T1_B) {
        int b = bid - T0_B;
        task = 1; ct = b % T1_CT; rc = b / T1_CT; RC = T1_RC;
        mat = Rm; ld = RDIM; cbias = br; cmeta = d_rmeta;
    } else {
        int b = bid - T0_B - T1_B;
        task = 2; ct = b % T2_CT; rc = b / T2_CT; RC = T2_RC;
        mat = Am; ld = RDIM; cbias = nullptr; cmeta = d_rmeta;
    }

    int u     = d_U[task];                 // unique row count (runtime)
    int chunk = (u + RC - 1) / RC;
    int r0    = rc * chunk;
    int nr    = min(chunk, u - r0);
    if (nr < 0) nr = 0;

    int c0 = ct * TILE_COLS + tid * COLS_PER_THREAD;
    bool colvalid = (c0 + COLS_PER_THREAD <= ld);   // dims are multiples of 4

    // stage row metadata into smem (precompute element offsets)
    for (int j = tid; j < nr; j += TPB) {
        int rr = r0 + j;
        if (task == 0)      { s_off[j] = d_r1i[rr] * GDIM; s_rv[j] = d_r1v[rr]; s_wb[j] = d_r1b[rr]; }
        else if (task == 1) { s_off[j] = d_r2i[rr] * RDIM; s_rv[j] = d_r2v[rr]; s_wb[j] = d_r2b[rr]; }
        else                { s_off[j] = d_rgi[rr] * RDIM; s_rv[j] = d_rgv[rr]; }
    }
    __syncthreads();

    float contrib = 0.f;

    if (colvalid) {
        if (task == 2) {
            float y0[4] = {0,0,0,0}, y1[4] = {0,0,0,0}, y2[4] = {0,0,0,0};
#pragma unroll 4
            for (int j = 0; j < nr; ++j) {
                const float4 x4 = ldcs4(mat + (size_t)(unsigned)s_off[j] + c0);
                float4 rv = s_rv[j];          // (w*p0, w*p1, w*p2, -)
                float xx[4] = {x4.x, x4.y, x4.z, x4.w};
#pragma unroll
                for (int c = 0; c < 4; c++) {
                    y0[c] += rv.x * xx[c];
                    y1[c] += rv.y * xx[c];
                    y2[c] += rv.z * xx[c];
                }
            }
#pragma unroll
            for (int c = 0; c < 4; c++) {
                float4 cm = __ldg(&cmeta[c0 + c]);   // (p0,p1,p2,w)
                contrib += cm.w * (cm.x * y0[c] + cm.y * y1[c] + cm.z * y2[c]);
            }
        } else {
            float y0[4] = {0,0,0,0}, y1[4] = {0,0,0,0}, y2[4] = {0,0,0,0};
            float s1[4] = {0,0,0,0}, sq[4] = {0,0,0,0}, sb[4] = {0,0,0,0};
#pragma unroll 4
            for (int j = 0; j < nr; ++j) {
                const float4 x4 = ldcs4(mat + (size_t)(unsigned)s_off[j] + c0);
                float4 rv = s_rv[j];          // (w*q0, w*q1, w*q2, w)
                float wb  = s_wb[j];          // w*b
                float xx[4] = {x4.x, x4.y, x4.z, x4.w};
#pragma unroll
                for (int c = 0; c < 4; c++) {
                    float x = xx[c];
                    y0[c] += rv.x * x;
                    y1[c] += rv.y * x;
                    y2[c] += rv.z * x;
                    float tw = rv.w * x;
                    s1[c] += tw;
                    sq[c] += tw * x;
                    sb[c] += wb * x;
                }
            }
#pragma unroll
            for (int c = 0; c < 4; c++) {
                float4 cm = __ldg(&cmeta[c0 + c]);
                float bgv = __ldg(&cbias[c0 + c]);
                float dotv = cm.x * y0[c] + cm.y * y1[c] + cm.z * y2[c];
                contrib += cm.w * (sq[c] - 2.f * (dotv + bgv * s1[c] + sb[c]));
            }
        }
    }

    // block reduce -> one double atomic per block
    s_red[tid] = contrib;
    __syncthreads();
    for (int s = TPB / 2; s > 0; s >>= 1) {
        if (tid < s) s_red[tid] += s_red[tid + s];
        __syncthreads();
    }
    if (tid == 0) atomicAdd(&d_T[task], (double)s_red[0]);

    // ---- last-block finalize (ticket; no cross-block spin) ----
    __threadfence();
    if (tid == 0) {
        int ticket = atomicAdd(&d_done, 1);
        s_last = (ticket == TOTAL_B - 1) ? 1 : 0;
    }
    __syncthreads();
    if (!s_last) return;
    __threadfence();   // acquire: all d_T/d_sums writes are globally visible

    // stage moments + pair sums (parallel loads, latencies overlap)
    if (tid < 64)      s_fin[tid] = d_sums[tid];
    else if (tid < 67) s_fin[tid] = d_T[tid - 64];
    __syncthreads();

    if (tid == 0) {
        const double* g  = &s_fin[0];
        const double* rr = &s_fin[16];
        const double* r1 = &s_fin[32];
        const double* r2 = &s_fin[48];
        double T1 = s_fin[64], T2 = s_fin[65], T3 = s_fin[66];

        double s1 = T1
                  + contract6s(&r1[0], &g[0])
                  + 2.0 * (dot3s(&r1[6], &g[9]) + dot3s(&r1[9], &g[6]))
                  + ((double)MM1 * g[13] + 2.0 * r1[12] * g[12] + (double)MMG * r1[13]);
        double loss1 = s1 / ((double)MM1 * (double)MMG);

        double s2 = T2
                  + contract6s(&r2[0], &rr[0])
                  + 2.0 * (dot3s(&r2[6], &rr[9]) + dot3s(&r2[9], &rr[6]))
                  + ((double)MM2 * rr[13] + 2.0 * r2[12] * rr[12] + (double)MMR * r2[13]);
        double loss2 = s2 / ((double)MM2 * (double)MMR);

        double loss3 = -T3 / sqrt(g[14] * rr[14]);

        double t1 = 1000.0 * loss1;
        double t2 = 1000.0 * loss2;
        double t3 = 100.0  * loss3;
        out[0] = (float)(t1 + t2 + t3);   // ALPHA[3] = 0 -> loss4 contributes 0
        out[1] = (float)t1;
        out[2] = (float)t2;
        out[3] = (float)t3;
        out[4] = 0.0f;
    }

    // reset scalar scratch for the next graph replay (parallel)
    if (tid < 64)       d_sums[tid] = 0.0;
    else if (tid < 67)  d_T[tid - 64] = 0.0;
    else if (tid < 71)  d_U[tid - 67] = 0;
    else if (tid == 71) d_done = 0;
}

// ---------------- launch ------------------------------------------------------
extern "C" void kernel_launch(void* const* d_in, const int* in_sizes, int n_in,
                              void* d_out, int out_size) {
    const float* G  = (const float*)d_in[0];
    const float* R  = (const float*)d_in[1];
    const float* A  = (const float*)d_in[2];
    const float* C1 = (const float*)d_in[3];
    const float* C2 = (const float*)d_in[4];
    const float* Cg = (const float*)d_in[5];
    const float* Cr = (const float*)d_in[6];
    const float* Ai = (const float*)d_in[7];
    const float* bg = (const float*)d_in[8];
    const float* br = (const float*)d_in[9];
    const float* b1 = (const float*)d_in[10];
    const float* b2 = (const float*)d_in[11];
    const int*   m1 = (const int*)d_in[12];
    const int*   m2 = (const int*)d_in[13];
    const int*   mg = (const int*)d_in[14];
    const int*   mr = (const int*)d_in[15];
    float* out = (float*)d_out;

    (void)in_sizes; (void)n_in; (void)out_size;

    const int nmask = MM1 + MM2 + MMG + MMR;   // 10800

    k_count<<<(nmask + 255) / 256, 256>>>(m1, m2, mg, mr);
    k_compact<<<COMPACT_BLOCKS, TPB>>>(C1, C2, Cg, Cr, Ai, bg, br, b1, b2);
    k_pair<<<TOTAL_B, TPB>>>(G, R, A, bg, br, out);
}